// round 9
// baseline (speedup 1.0000x reference)
#include <cuda_runtime.h>
#include <cuda_bf16.h>
#include <mma.h>

using namespace nvcuda;

// Problem constants
#define TT 512
#define BB 64
#define EE 512
#define HH 1024
#define G3 3072      // 3 gates * H, gate order: g, i, o
#define NCTA_REC 128 // persistent recurrence grid (64 h-tiles x 2 n-halves)

// ---------------------------------------------------------------------------
// Static device scratch (allocation-free rule: __device__ globals)
// ---------------------------------------------------------------------------
__device__ __align__(16) float         g_xz[(size_t)TT * G3 * BB];       // preactivations [T][3H][B]
__device__ __align__(16) __nv_bfloat16 g_xt_hi[(size_t)TT * EE * BB];    // embeds transposed [T][E][B]
__device__ __align__(16) __nv_bfloat16 g_xt_lo[(size_t)TT * EE * BB];
__device__ __align__(16) __nv_bfloat16 g_wx_hi[(size_t)G3 * EE];         // [3H][E] gate-major
__device__ __align__(16) __nv_bfloat16 g_wx_lo[(size_t)G3 * EE];
__device__ __align__(16) __nv_bfloat16 g_wh_hi[(size_t)G3 * HH];         // [3H][H] gate-major
__device__ __align__(16) __nv_bfloat16 g_wh_lo[(size_t)G3 * HH];
__device__ __align__(16) __nv_bfloat16 g_c_hi[2][(size_t)HH * BB];       // ping-pong carry c (bf16 hi/lo)
__device__ __align__(16) __nv_bfloat16 g_c_lo[2][(size_t)HH * BB];

// grid-barrier state (zero-initialized; g_cnt returns to 0 after every barrier)
__device__ unsigned g_bar_cnt;
__device__ unsigned g_bar_gen;

// ---------------------------------------------------------------------------
// Device-wide sense-reversing barrier (all NCTA_REC CTAs co-resident)
// ---------------------------------------------------------------------------
__device__ __forceinline__ void grid_bar()
{
    __syncthreads();
    if (threadIdx.x == 0) {
        __threadfence();                                   // release our c writes
        unsigned gen = atomicAdd(&g_bar_gen, 0u);          // read current generation
        __threadfence();                                   // order gen-read before cnt-inc
        if (atomicAdd(&g_bar_cnt, 1u) == NCTA_REC - 1u) {
            atomicExch(&g_bar_cnt, 0u);
            __threadfence();
            atomicAdd(&g_bar_gen, 1u);                     // release everyone
        } else {
            while (atomicAdd(&g_bar_gen, 0u) == gen) __nanosleep(64);
        }
        __threadfence();                                   // acquire others' c writes
    }
    __syncthreads();
}

// ---------------------------------------------------------------------------
// Split fp32 -> bf16 hi/lo
// ---------------------------------------------------------------------------
__global__ void split_kernel(const float* __restrict__ src,
                             __nv_bfloat16* __restrict__ hi,
                             __nv_bfloat16* __restrict__ lo, int n)
{
    int i = blockIdx.x * blockDim.x + threadIdx.x;
    if (i < n) {
        float v = src[i];
        __nv_bfloat16 h = __float2bfloat16(v);
        hi[i] = h;
        lo[i] = __float2bfloat16(v - __bfloat162float(h));
    }
}

// embeds [T][B][E] -> transposed split [T][E][B]
__global__ void transpose_split_kernel(const float* __restrict__ emb,
                                       __nv_bfloat16* __restrict__ hi,
                                       __nv_bfloat16* __restrict__ lo)
{
    long i = (long)blockIdx.x * blockDim.x + threadIdx.x;   // over T*E*B
    if (i < (long)TT * EE * BB) {
        int  b  = (int)(i & (BB - 1));
        long te = i >> 6;
        int  e  = (int)(te & (EE - 1));
        int  t  = (int)(te >> 9);
        float v = emb[((long)t * BB + b) * EE + e];
        __nv_bfloat16 h = __float2bfloat16(v);
        hi[i] = h;
        lo[i] = __float2bfloat16(v - __bfloat162float(h));
    }
}

__global__ void zero_c_kernel(__nv_bfloat16* __restrict__ chi,
                              __nv_bfloat16* __restrict__ clo)
{
    int i = blockIdx.x * blockDim.x + threadIdx.x;
    if (i < HH * BB) {
        chi[i] = __float2bfloat16(0.0f);
        clo[i] = __float2bfloat16(0.0f);
    }
}

// ---------------------------------------------------------------------------
// Phase 1: split-bf16 WMMA GEMM over all timesteps
//   C[t] = Wx[3072,512] * X[t][512,64], fp32 out.
//   blockIdx.x = m-tile (32 rows, 96 tiles), blockIdx.y = t. 2 warps/CTA.
// ---------------------------------------------------------------------------
__global__ __launch_bounds__(64)
void gemm_split_kernel(const __nv_bfloat16* __restrict__ Ah,
                       const __nv_bfloat16* __restrict__ Al,
                       const __nv_bfloat16* __restrict__ Bh_base,
                       const __nv_bfloat16* __restrict__ Bl_base,
                       float* __restrict__ C_base,
                       int K)
{
    const int m0 = blockIdx.x * 32;
    const long y = blockIdx.y;
    const __nv_bfloat16* Bh = Bh_base + y * K * 64;
    const __nv_bfloat16* Bl = Bl_base + y * K * 64;
    float* C = C_base + y * (long)G3 * 64;

    __shared__ __align__(16) __nv_bfloat16 As[2][32][16];
    __shared__ __align__(16) __nv_bfloat16 Bs[2][16][64];

    const int tid  = threadIdx.x;
    const int warp = tid >> 5;

    wmma::fragment<wmma::accumulator, 16, 16, 16, float> acc[4];
#pragma unroll
    for (int i = 0; i < 4; i++) wmma::fill_fragment(acc[i], 0.0f);

    for (int kc = 0; kc < K; kc += 16) {
        {
            int r  = tid >> 1;
            int h8 = (tid & 1) * 8;
            size_t off = (size_t)(m0 + r) * K + kc + h8;
            *(uint4*)&As[0][r][h8] = *(const uint4*)&Ah[off];
            *(uint4*)&As[1][r][h8] = *(const uint4*)&Al[off];
        }
#pragma unroll
        for (int u = tid; u < 128; u += 64) {
            int r  = u >> 3;
            int c8 = (u & 7) * 8;
            size_t off = (size_t)(kc + r) * 64 + c8;
            *(uint4*)&Bs[0][r][c8] = *(const uint4*)&Bh[off];
            *(uint4*)&Bs[1][r][c8] = *(const uint4*)&Bl[off];
        }
        __syncthreads();

        wmma::fragment<wmma::matrix_a, 16, 16, 16, __nv_bfloat16, wmma::row_major> a_hi, a_lo;
        wmma::load_matrix_sync(a_hi, &As[0][warp * 16][0], 16);
        wmma::load_matrix_sync(a_lo, &As[1][warp * 16][0], 16);
#pragma unroll
        for (int nf = 0; nf < 4; nf++) {
            wmma::fragment<wmma::matrix_b, 16, 16, 16, __nv_bfloat16, wmma::row_major> b_hi, b_lo;
            wmma::load_matrix_sync(b_hi, &Bs[0][0][nf * 16], 64);
            wmma::load_matrix_sync(b_lo, &Bs[1][0][nf * 16], 64);
            wmma::mma_sync(acc[nf], a_hi, b_hi, acc[nf]);
            wmma::mma_sync(acc[nf], a_hi, b_lo, acc[nf]);
            wmma::mma_sync(acc[nf], a_lo, b_hi, acc[nf]);
        }
        __syncthreads();
    }

#pragma unroll
    for (int nf = 0; nf < 4; nf++)
        wmma::store_matrix_sync(&C[(size_t)(m0 + warp * 16) * 64 + nf * 16],
                                acc[nf], 64, wmma::mem_row_major);
}

// ---------------------------------------------------------------------------
// Phase 2: persistent recurrence kernel. 128 CTAs x 192 threads (6 warps).
//   CTA (htile, nhalf) owns rows [h0,h0+16) x cols [n0,n0+32) of ALL 3 gates.
//   Warp w: gate = w/2, n-frag = w%2 (16x16 accumulator, K=1024 split-bf16).
//   Carry c is ping-pong buffered; one grid barrier per step.
//   c is read via __ldcg (L2-coherent); weights read direct from gmem (L1-resident).
// ---------------------------------------------------------------------------
__global__ __launch_bounds__(192)
void recurrence_kernel(const __nv_bfloat16* __restrict__ Wh_hi,
                       const __nv_bfloat16* __restrict__ Wh_lo,
                       const float* __restrict__ xz,
                       const float* __restrict__ bg,
                       const float* __restrict__ bi,
                       const float* __restrict__ bo,
                       __nv_bfloat16* __restrict__ c_hi,   // [2][H*B]
                       __nv_bfloat16* __restrict__ c_lo,   // [2][H*B]
                       float* __restrict__ out)
{
    const int cta   = blockIdx.x;
    const int h0    = (cta >> 1) * 16;    // h-tile base
    const int n0    = (cta & 1) * 32;     // batch-half base
    const int tid   = threadIdx.x;
    const int warp  = tid >> 5;           // 0..5
    const int gate  = warp >> 1;          // 0..2
    const int nf    = warp & 1;           // 0..1

    __shared__ __align__(16) __nv_bfloat16 Bs_hi[64][32];
    __shared__ __align__(16) __nv_bfloat16 Bs_lo[64][32];
    __shared__ __align__(16) float         Ps[3][16][32];

    const __nv_bfloat16* Ah = Wh_hi + (size_t)(gate * HH + h0) * HH;
    const __nv_bfloat16* Al = Wh_lo + (size_t)(gate * HH + h0) * HH;
    const float* bias = (gate == 0) ? bg : (gate == 1) ? bi : bo;
    (void)bias;

    for (int t = 0; t < TT; t++) {
        const int rb = t & 1;                                     // read buffer
        const __nv_bfloat16* Ch = c_hi + (size_t)rb * HH * BB;
        const __nv_bfloat16* Cl = c_lo + (size_t)rb * HH * BB;
        __nv_bfloat16* Wch = c_hi + (size_t)(rb ^ 1) * HH * BB;   // write buffer
        __nv_bfloat16* Wcl = c_lo + (size_t)(rb ^ 1) * HH * BB;

        wmma::fragment<wmma::accumulator, 16, 16, 16, float> acc;
        wmma::fill_fragment(acc, 0.0f);

        for (int kc = 0; kc < HH; kc += 64) {
            // stage Bs: c rows [kc,kc+64) x cols [n0,n0+32), hi + lo (L2-coherent loads)
#pragma unroll
            for (int u = tid; u < 512; u += 192) {
                int m  = u >> 8;          // 0 = hi, 1 = lo
                int v  = u & 255;
                int r  = v >> 2;          // 0..63
                int c8 = (v & 3) * 8;     // 0,8,16,24
                const __nv_bfloat16* src = (m ? Cl : Ch) + (size_t)(kc + r) * BB + n0 + c8;
                uint4 val = __ldcg((const uint4*)src);
                if (m) *(uint4*)&Bs_lo[r][c8] = val;
                else   *(uint4*)&Bs_hi[r][c8] = val;
            }
            __syncthreads();

#pragma unroll
            for (int kk = 0; kk < 64; kk += 16) {
                wmma::fragment<wmma::matrix_a, 16, 16, 16, __nv_bfloat16, wmma::row_major> a_hi, a_lo;
                wmma::load_matrix_sync(a_hi, Ah + kc + kk, HH);
                wmma::load_matrix_sync(a_lo, Al + kc + kk, HH);
                wmma::fragment<wmma::matrix_b, 16, 16, 16, __nv_bfloat16, wmma::row_major> b_hi, b_lo;
                wmma::load_matrix_sync(b_hi, &Bs_hi[kk][nf * 16], 32);
                wmma::load_matrix_sync(b_lo, &Bs_lo[kk][nf * 16], 32);
                wmma::mma_sync(acc, a_hi, b_hi, acc);
                wmma::mma_sync(acc, a_hi, b_lo, acc);
                wmma::mma_sync(acc, a_lo, b_hi, acc);
            }
            __syncthreads();
        }

        // exchange accumulators CTA-locally
        wmma::store_matrix_sync(&Ps[gate][0][nf * 16], acc, 32, wmma::mem_row_major);
        __syncthreads();

        // combine for this CTA's 16x32 block
        const float* xzt = xz + (size_t)t * G3 * BB;
#pragma unroll
        for (int i = tid; i < 512; i += 192) {
            int hl = i >> 5;              // 0..15
            int bl = i & 31;              // 0..31
            int h  = h0 + hl;
            int b  = n0 + bl;
            float pg = Ps[0][hl][bl] + xzt[(size_t)(0 * HH + h) * BB + b] + bg[h];
            float pi = Ps[1][hl][bl] + xzt[(size_t)(1 * HH + h) * BB + b] + bi[h];
            float po = Ps[2][hl][bl] + xzt[(size_t)(2 * HH + h) * BB + b] + bo[h];
            float g  = tanhf(pg);
            float si = 1.0f / (1.0f + expf(-pi));
            float so = 1.0f / (1.0f + expf(-po));
            float c  = g * si;
            float hv = tanhf(c) * so;
            __nv_bfloat16 ch = __float2bfloat16(c);
            Wch[(size_t)h * BB + b] = ch;
            Wcl[(size_t)h * BB + b] = __float2bfloat16(c - __bfloat162float(ch));
            out[(size_t)t * BB * HH + (size_t)b * HH + h] = hv;
        }

        grid_bar();   // all combine writes visible before anyone reads next step's c
    }
}

// ---------------------------------------------------------------------------
// kernel_launch — graph-capturable; ~10 kernel nodes total
// ---------------------------------------------------------------------------
extern "C" void kernel_launch(void* const* d_in, const int* in_sizes, int n_in,
                              void* d_out, int out_size)
{
    const float* embeds = (const float*)d_in[0];
    const float* Wgx = (const float*)d_in[1];
    const float* Wgh = (const float*)d_in[2];
    const float* bg  = (const float*)d_in[3];
    const float* Wix = (const float*)d_in[4];
    const float* Wih = (const float*)d_in[5];
    const float* bi  = (const float*)d_in[6];
    // d_in[7..9] = Wfx, Wfh, bf — dead in the reference (f gate multiplied by 0)
    const float* Wox = (const float*)d_in[10];
    const float* Woh = (const float*)d_in[11];
    const float* bo  = (const float*)d_in[12];
    float* out = (float*)d_out;

    float *p_xz;
    __nv_bfloat16 *p_xt_hi, *p_xt_lo, *p_wx_hi, *p_wx_lo, *p_wh_hi, *p_wh_lo, *p_c_hi, *p_c_lo;
    cudaGetSymbolAddress((void**)&p_xz,    g_xz);
    cudaGetSymbolAddress((void**)&p_xt_hi, g_xt_hi);
    cudaGetSymbolAddress((void**)&p_xt_lo, g_xt_lo);
    cudaGetSymbolAddress((void**)&p_wx_hi, g_wx_hi);
    cudaGetSymbolAddress((void**)&p_wx_lo, g_wx_lo);
    cudaGetSymbolAddress((void**)&p_wh_hi, g_wh_hi);
    cudaGetSymbolAddress((void**)&p_wh_lo, g_wh_lo);
    cudaGetSymbolAddress((void**)&p_c_hi,  g_c_hi);
    cudaGetSymbolAddress((void**)&p_c_lo,  g_c_lo);

    // 1) split weights into bf16 hi/lo, gate-major [g; i; o]
    {
        int nWx = HH * EE;
        int nWh = HH * HH;
        int blk = 256;
        split_kernel<<<(nWx + blk - 1) / blk, blk>>>(Wgx, p_wx_hi,            p_wx_lo,            nWx);
        split_kernel<<<(nWx + blk - 1) / blk, blk>>>(Wix, p_wx_hi + 1L * nWx, p_wx_lo + 1L * nWx, nWx);
        split_kernel<<<(nWx + blk - 1) / blk, blk>>>(Wox, p_wx_hi + 2L * nWx, p_wx_lo + 2L * nWx, nWx);
        split_kernel<<<(nWh + blk - 1) / blk, blk>>>(Wgh, p_wh_hi,            p_wh_lo,            nWh);
        split_kernel<<<(nWh + blk - 1) / blk, blk>>>(Wih, p_wh_hi + 1L * nWh, p_wh_lo + 1L * nWh, nWh);
        split_kernel<<<(nWh + blk - 1) / blk, blk>>>(Woh, p_wh_hi + 2L * nWh, p_wh_lo + 2L * nWh, nWh);
    }

    // 2) transpose+split embeds to [T][E][B]
    {
        long n = (long)TT * EE * BB;
        transpose_split_kernel<<<(unsigned)((n + 255) / 256), 256>>>(embeds, p_xt_hi, p_xt_lo);
    }

    // 3) input projections: XZ[t][3H][B] (bias added at combine)
    {
        dim3 grid(G3 / 32, TT);     // (96, 512)
        gemm_split_kernel<<<grid, 64>>>(p_wx_hi, p_wx_lo, p_xt_hi, p_xt_lo, p_xz, EE);
    }

    // 4) zero initial carry (read buffer 0 at t=0)
    zero_c_kernel<<<(HH * BB) / 256, 256>>>(p_c_hi, p_c_lo);

    // 5) persistent recurrence: ONE kernel for all 512 steps
    recurrence_kernel<<<NCTA_REC, 192>>>(p_wh_hi, p_wh_lo, p_xz,
                                         bg, bi, bo,
                                         p_c_hi, p_c_lo, out);
}

// round 11
// speedup vs baseline: 1.7378x; 1.7378x over previous
#include <cuda_runtime.h>
#include <cuda_bf16.h>
#include <cuda_pipeline.h>
#include <mma.h>

using namespace nvcuda;

// Problem constants
#define TT 512
#define BB 64
#define EE 512
#define HH 1024
#define G3 3072      // 3 gates * H, gate order: g, i, o
#define NCTA_REC 128 // persistent recurrence grid (64 h-tiles x 2 n-halves)

#define WS_LD 1032   // padded K stride for weight smem (conflict-free ldmatrix)
#define BS_LD 40     // padded batch stride for carry smem (conflict-free ldmatrix)
#define SMEM_WS (48 * WS_LD)  // elements per (hi|lo) weight matrix in smem
// bytes: weights 2*2*48*1032*2=198144, Bs 2buf*2mat*64*40*2=20480,
//        Ps 3*16*32*4=6144, Hs 32*16*4=2048  -> total 226816 (< 227KB limit)
#define SMEM_REC_BYTES 226816

// ---------------------------------------------------------------------------
// Static device scratch (allocation-free rule: __device__ globals)
// ---------------------------------------------------------------------------
__device__ __align__(16) float         g_xz[(size_t)TT * G3 * BB];       // preactivations [T][3H][B]
__device__ __align__(16) __nv_bfloat16 g_xt_hi[(size_t)TT * EE * BB];    // embeds transposed [T][E][B]
__device__ __align__(16) __nv_bfloat16 g_xt_lo[(size_t)TT * EE * BB];
__device__ __align__(16) __nv_bfloat16 g_wx_hi[(size_t)G3 * EE];         // [3H][E] gate-major
__device__ __align__(16) __nv_bfloat16 g_wx_lo[(size_t)G3 * EE];
__device__ __align__(16) __nv_bfloat16 g_wh_hi[(size_t)G3 * HH];         // [3H][H] gate-major
__device__ __align__(16) __nv_bfloat16 g_wh_lo[(size_t)G3 * HH];
__device__ __align__(16) __nv_bfloat16 g_c_hi[2][(size_t)HH * BB];       // ping-pong carry c (bf16 hi/lo)
__device__ __align__(16) __nv_bfloat16 g_c_lo[2][(size_t)HH * BB];

// grid-barrier state (zero-initialized; g_bar_cnt returns to 0 after every barrier)
__device__ unsigned g_bar_cnt;
__device__ unsigned g_bar_gen;

// ---------------------------------------------------------------------------
// Device-wide sense-reversing barrier (all NCTA_REC CTAs co-resident, 1/SM)
// ---------------------------------------------------------------------------
__device__ __forceinline__ void grid_bar()
{
    __syncthreads();
    if (threadIdx.x == 0) {
        __threadfence();                                   // release our c writes
        unsigned gen = atomicAdd(&g_bar_gen, 0u);          // read current generation
        __threadfence();
        if (atomicAdd(&g_bar_cnt, 1u) == NCTA_REC - 1u) {
            atomicExch(&g_bar_cnt, 0u);
            __threadfence();
            atomicAdd(&g_bar_gen, 1u);                     // release everyone
        } else {
            while (atomicAdd(&g_bar_gen, 0u) == gen) __nanosleep(64);
        }
        __threadfence();                                   // acquire others' c writes
    }
    __syncthreads();
}

// ---------------------------------------------------------------------------
// Fused split: all 6 weight matrices fp32 -> bf16 hi/lo, gate-major [g; i; o]
// ---------------------------------------------------------------------------
__global__ void split6_kernel(const float* __restrict__ Wgx, const float* __restrict__ Wix,
                              const float* __restrict__ Wox, const float* __restrict__ Wgh,
                              const float* __restrict__ Wih, const float* __restrict__ Woh,
                              __nv_bfloat16* __restrict__ wx_hi, __nv_bfloat16* __restrict__ wx_lo,
                              __nv_bfloat16* __restrict__ wh_hi, __nv_bfloat16* __restrict__ wh_lo)
{
    long i = (long)blockIdx.x * blockDim.x + threadIdx.x;
    const long nWx = (long)HH * EE, nWh = (long)HH * HH;
    float v;
    __nv_bfloat16 *hi, *lo;
    long idx;
    if (i < 3 * nWx) {
        int g = (int)(i / nWx);
        long j = i - (long)g * nWx;
        const float* src = (g == 0) ? Wgx : (g == 1) ? Wix : Wox;
        v = src[j]; hi = wx_hi; lo = wx_lo; idx = i;
    } else {
        long k = i - 3 * nWx;
        if (k >= 3 * nWh) return;
        int g = (int)(k / nWh);
        long j = k - (long)g * nWh;
        const float* src = (g == 0) ? Wgh : (g == 1) ? Wih : Woh;
        v = src[j]; hi = wh_hi; lo = wh_lo; idx = k;
    }
    __nv_bfloat16 h = __float2bfloat16(v);
    hi[idx] = h;
    lo[idx] = __float2bfloat16(v - __bfloat162float(h));
}

// embeds [T][B][E] -> transposed split [T][E][B]
__global__ void transpose_split_kernel(const float* __restrict__ emb,
                                       __nv_bfloat16* __restrict__ hi,
                                       __nv_bfloat16* __restrict__ lo)
{
    long i = (long)blockIdx.x * blockDim.x + threadIdx.x;   // over T*E*B
    if (i < (long)TT * EE * BB) {
        int  b  = (int)(i & (BB - 1));
        long te = i >> 6;
        int  e  = (int)(te & (EE - 1));
        int  t  = (int)(te >> 9);
        float v = emb[((long)t * BB + b) * EE + e];
        __nv_bfloat16 h = __float2bfloat16(v);
        hi[i] = h;
        lo[i] = __float2bfloat16(v - __bfloat162float(h));
    }
}

// ---------------------------------------------------------------------------
// Phase 1: split-bf16 WMMA GEMM over all timesteps
//   C[t] = Wx[3072,512] * X[t][512,64], fp32 out.
//   blockIdx.x = m-tile (32 rows, 96 tiles), blockIdx.y = t. 2 warps/CTA.
// ---------------------------------------------------------------------------
__global__ __launch_bounds__(64)
void gemm_split_kernel(const __nv_bfloat16* __restrict__ Ah,
                       const __nv_bfloat16* __restrict__ Al,
                       const __nv_bfloat16* __restrict__ Bh_base,
                       const __nv_bfloat16* __restrict__ Bl_base,
                       float* __restrict__ C_base,
                       int K)
{
    const int m0 = blockIdx.x * 32;
    const long y = blockIdx.y;
    const __nv_bfloat16* Bh = Bh_base + y * K * 64;
    const __nv_bfloat16* Bl = Bl_base + y * K * 64;
    float* C = C_base + y * (long)G3 * 64;

    __shared__ __align__(16) __nv_bfloat16 As[2][32][16];
    __shared__ __align__(16) __nv_bfloat16 Bs[2][16][64];

    const int tid  = threadIdx.x;
    const int warp = tid >> 5;

    wmma::fragment<wmma::accumulator, 16, 16, 16, float> acc[4];
#pragma unroll
    for (int i = 0; i < 4; i++) wmma::fill_fragment(acc[i], 0.0f);

    for (int kc = 0; kc < K; kc += 16) {
        {
            int r  = tid >> 1;
            int h8 = (tid & 1) * 8;
            size_t off = (size_t)(m0 + r) * K + kc + h8;
            *(uint4*)&As[0][r][h8] = *(const uint4*)&Ah[off];
            *(uint4*)&As[1][r][h8] = *(const uint4*)&Al[off];
        }
#pragma unroll
        for (int u = tid; u < 128; u += 64) {
            int r  = u >> 3;
            int c8 = (u & 7) * 8;
            size_t off = (size_t)(kc + r) * 64 + c8;
            *(uint4*)&Bs[0][r][c8] = *(const uint4*)&Bh[off];
            *(uint4*)&Bs[1][r][c8] = *(const uint4*)&Bl[off];
        }
        __syncthreads();

        wmma::fragment<wmma::matrix_a, 16, 16, 16, __nv_bfloat16, wmma::row_major> a_hi, a_lo;
        wmma::load_matrix_sync(a_hi, &As[0][warp * 16][0], 16);
        wmma::load_matrix_sync(a_lo, &As[1][warp * 16][0], 16);
#pragma unroll
        for (int nf = 0; nf < 4; nf++) {
            wmma::fragment<wmma::matrix_b, 16, 16, 16, __nv_bfloat16, wmma::row_major> b_hi, b_lo;
            wmma::load_matrix_sync(b_hi, &Bs[0][0][nf * 16], 64);
            wmma::load_matrix_sync(b_lo, &Bs[1][0][nf * 16], 64);
            wmma::mma_sync(acc[nf], a_hi, b_hi, acc[nf]);
            wmma::mma_sync(acc[nf], a_hi, b_lo, acc[nf]);
            wmma::mma_sync(acc[nf], a_lo, b_hi, acc[nf]);
        }
        __syncthreads();
    }

#pragma unroll
    for (int nf = 0; nf < 4; nf++)
        wmma::store_matrix_sync(&C[(size_t)(m0 + warp * 16) * 64 + nf * 16],
                                acc[nf], 64, wmma::mem_row_major);
}

// ---------------------------------------------------------------------------
// Phase 2: persistent recurrence. 128 CTAs x 192 threads (6 warps).
//   CTA (htile, nhalf) owns rows [h0,h0+16) x cols [n0,n0+32) of ALL 3 gates.
//   Weights (192KB/CTA) preloaded into padded smem ONCE; carry staged per
//   64-K chunk with double-buffered 16B cp.async (.cg -> L1-bypassing, so
//   cross-SM carry writes are always seen fresh from L2).
// ---------------------------------------------------------------------------
__global__ __launch_bounds__(192)
void recurrence_kernel(const __nv_bfloat16* __restrict__ Wh_hi,
                       const __nv_bfloat16* __restrict__ Wh_lo,
                       const float* __restrict__ xz,
                       const float* __restrict__ bg,
                       const float* __restrict__ bi,
                       const float* __restrict__ bo,
                       __nv_bfloat16* __restrict__ c_hi,   // [2][H*B]
                       __nv_bfloat16* __restrict__ c_lo,   // [2][H*B]
                       float* __restrict__ out)
{
    extern __shared__ __align__(128) char smem_raw[];
    __nv_bfloat16* ws_hi = (__nv_bfloat16*)smem_raw;        // [48][WS_LD]
    __nv_bfloat16* ws_lo = ws_hi + SMEM_WS;
    __nv_bfloat16* bs    = ws_lo + SMEM_WS;                 // [2 buf][2 mat][64][BS_LD]
    float* Ps = (float*)(bs + 2 * 2 * 64 * BS_LD);          // [3][16][32]
    float* Hs = Ps + 3 * 16 * 32;                           // [32][16]

    const int cta  = blockIdx.x;
    const int h0   = (cta >> 1) * 16;    // h-tile base
    const int n0   = (cta & 1) * 32;     // batch-half base
    const int tid  = threadIdx.x;
    const int warp = tid >> 5;           // 0..5
    const int gate = warp >> 1;          // 0..2
    const int nf   = warp & 1;           // 0..1

    // ---- one-time: preload this CTA's 48x1024 hi/lo weight rows into smem
    for (int u = tid; u < 2 * 48 * 128; u += 192) {
        int m  = (u >= 6144);
        int v  = m ? u - 6144 : u;
        int r  = v >> 7;                  // local row 0..47 (= gate*16 + hl)
        int c8 = (v & 127) * 8;           // element col
        int g  = r >> 4, hl = r & 15;
        const __nv_bfloat16* src = (m ? Wh_lo : Wh_hi) + (size_t)(g * HH + h0 + hl) * HH + c8;
        __nv_bfloat16* dst = (m ? ws_lo : ws_hi) + r * WS_LD + c8;
        *(uint4*)dst = *(const uint4*)src;
    }

    // ---- one-time: zero owned slice of carry buffer 0
    for (int u = tid; u < 512; u += 192) {
        int hl = u >> 5, bl = u & 31;
        size_t off = (size_t)(h0 + hl) * BB + n0 + bl;
        c_hi[off] = __float2bfloat16(0.0f);
        c_lo[off] = __float2bfloat16(0.0f);
    }
    grid_bar();   // also publishes smem weight preload (via its __syncthreads)

    // cp.async stage of one 64-row K chunk of the carry (hi+lo), 16B chunks
    auto stage = [&](const __nv_bfloat16* Ch, const __nv_bfloat16* Cl, int kc, int buf) {
        __nv_bfloat16* bh  = bs + (buf * 2 + 0) * 64 * BS_LD;
        __nv_bfloat16* blo = bs + (buf * 2 + 1) * 64 * BS_LD;
        for (int u = tid; u < 512; u += 192) {
            int m  = u >> 8;              // 0 = hi, 1 = lo
            int v  = u & 255;
            int r  = v >> 2;              // 0..63
            int c8 = (v & 3) * 8;         // element col 0,8,16,24
            const __nv_bfloat16* src = (m ? Cl : Ch) + (size_t)(kc + r) * BB + n0 + c8;
            __nv_bfloat16* dst = (m ? blo : bh) + r * BS_LD + c8;
            __pipeline_memcpy_async(dst, src, 16);   // 16B -> cp.async.cg (L1 bypass)
        }
    };

    const __nv_bfloat16* arow_hi = ws_hi + gate * 16 * WS_LD;
    const __nv_bfloat16* arow_lo = ws_lo + gate * 16 * WS_LD;

    for (int t = 0; t < TT; t++) {
        const int rb = t & 1;
        const __nv_bfloat16* Ch = c_hi + (size_t)rb * HH * BB;
        const __nv_bfloat16* Cl = c_lo + (size_t)rb * HH * BB;
        __nv_bfloat16* Wch = c_hi + (size_t)(rb ^ 1) * HH * BB;
        __nv_bfloat16* Wcl = c_lo + (size_t)(rb ^ 1) * HH * BB;

        wmma::fragment<wmma::accumulator, 16, 16, 16, float> acc;
        wmma::fill_fragment(acc, 0.0f);

        stage(Ch, Cl, 0, 0);
        __pipeline_commit();

        for (int kci = 0; kci < 16; kci++) {
            const int buf = kci & 1;
            if (kci + 1 < 16) {
                stage(Ch, Cl, (kci + 1) * 64, buf ^ 1);
                __pipeline_commit();
                __pipeline_wait_prior(1);
            } else {
                __pipeline_wait_prior(0);
            }
            __syncthreads();

            const __nv_bfloat16* bh  = bs + (buf * 2 + 0) * 64 * BS_LD + nf * 16;
            const __nv_bfloat16* blo = bs + (buf * 2 + 1) * 64 * BS_LD + nf * 16;
#pragma unroll
            for (int kk = 0; kk < 4; kk++) {
                wmma::fragment<wmma::matrix_a, 16, 16, 16, __nv_bfloat16, wmma::row_major> a_hi, a_lo;
                wmma::load_matrix_sync(a_hi, arow_hi + kci * 64 + kk * 16, WS_LD);
                wmma::load_matrix_sync(a_lo, arow_lo + kci * 64 + kk * 16, WS_LD);
                wmma::fragment<wmma::matrix_b, 16, 16, 16, __nv_bfloat16, wmma::row_major> b_hi, b_lo;
                wmma::load_matrix_sync(b_hi, bh + kk * 16 * BS_LD, BS_LD);
                wmma::load_matrix_sync(b_lo, blo + kk * 16 * BS_LD, BS_LD);
                wmma::mma_sync(acc, a_hi, b_hi, acc);
                wmma::mma_sync(acc, a_hi, b_lo, acc);
                wmma::mma_sync(acc, a_lo, b_hi, acc);
            }
            __syncthreads();
        }

        // exchange accumulators CTA-locally
        wmma::store_matrix_sync(Ps + gate * 512 + nf * 16, acc, 32, wmma::mem_row_major);
        __syncthreads();

        // combine for this CTA's 16x32 block (b-fastest mapping: coalesced xz reads)
        const float* xzt = xz + (size_t)t * G3 * BB;
        for (int i = tid; i < 512; i += 192) {
            int hl = i >> 5, bl = i & 31;
            int h = h0 + hl, b = n0 + bl;
            float pg = Ps[0 * 512 + hl * 32 + bl] + xzt[(size_t)(0 * HH + h) * BB + b] + bg[h];
            float pi = Ps[1 * 512 + hl * 32 + bl] + xzt[(size_t)(1 * HH + h) * BB + b] + bi[h];
            float po = Ps[2 * 512 + hl * 32 + bl] + xzt[(size_t)(2 * HH + h) * BB + b] + bo[h];
            float g  = tanhf(pg);
            float si = 1.0f / (1.0f + expf(-pi));
            float so = 1.0f / (1.0f + expf(-po));
            float c  = g * si;
            float hv = tanhf(c) * so;
            __nv_bfloat16 chh = __float2bfloat16(c);
            Wch[(size_t)h * BB + b] = chh;
            Wcl[(size_t)h * BB + b] = __float2bfloat16(c - __bfloat162float(chh));
            Hs[bl * 16 + hl] = hv;
        }
        __syncthreads();

        // coalesced out writes (h-fastest mapping through the smem bounce tile)
        for (int j = tid; j < 512; j += 192) {
            int hI = j & 15, bI = j >> 4;
            out[(size_t)t * BB * HH + (size_t)(n0 + bI) * HH + h0 + hI] = Hs[bI * 16 + hI];
        }

        grid_bar();   // all carry writes visible before next step's cp.async reads
    }
}

// ---------------------------------------------------------------------------
// kernel_launch — graph-capturable; 4 kernel nodes total
// ---------------------------------------------------------------------------
extern "C" void kernel_launch(void* const* d_in, const int* in_sizes, int n_in,
                              void* d_out, int out_size)
{
    const float* embeds = (const float*)d_in[0];
    const float* Wgx = (const float*)d_in[1];
    const float* Wgh = (const float*)d_in[2];
    const float* bg  = (const float*)d_in[3];
    const float* Wix = (const float*)d_in[4];
    const float* Wih = (const float*)d_in[5];
    const float* bi  = (const float*)d_in[6];
    // d_in[7..9] = Wfx, Wfh, bf — dead in the reference (f gate multiplied by 0)
    const float* Wox = (const float*)d_in[10];
    const float* Woh = (const float*)d_in[11];
    const float* bo  = (const float*)d_in[12];
    float* out = (float*)d_out;

    float *p_xz;
    __nv_bfloat16 *p_xt_hi, *p_xt_lo, *p_wx_hi, *p_wx_lo, *p_wh_hi, *p_wh_lo, *p_c_hi, *p_c_lo;
    cudaGetSymbolAddress((void**)&p_xz,    g_xz);
    cudaGetSymbolAddress((void**)&p_xt_hi, g_xt_hi);
    cudaGetSymbolAddress((void**)&p_xt_lo, g_xt_lo);
    cudaGetSymbolAddress((void**)&p_wx_hi, g_wx_hi);
    cudaGetSymbolAddress((void**)&p_wx_lo, g_wx_lo);
    cudaGetSymbolAddress((void**)&p_wh_hi, g_wh_hi);
    cudaGetSymbolAddress((void**)&p_wh_lo, g_wh_lo);
    cudaGetSymbolAddress((void**)&p_c_hi,  g_c_hi);
    cudaGetSymbolAddress((void**)&p_c_lo,  g_c_lo);

    cudaFuncSetAttribute(recurrence_kernel,
                         cudaFuncAttributeMaxDynamicSharedMemorySize, SMEM_REC_BYTES);

    // 1) split all 6 weight matrices into bf16 hi/lo (one launch)
    {
        long total = 3L * HH * EE + 3L * HH * HH;   // 4,718,592
        split6_kernel<<<(unsigned)((total + 255) / 256), 256>>>(
            Wgx, Wix, Wox, Wgh, Wih, Woh, p_wx_hi, p_wx_lo, p_wh_hi, p_wh_lo);
    }

    // 2) transpose+split embeds to [T][E][B]
    {
        long n = (long)TT * EE * BB;
        transpose_split_kernel<<<(unsigned)((n + 255) / 256), 256>>>(embeds, p_xt_hi, p_xt_lo);
    }

    // 3) input projections: XZ[t][3H][B] (bias added at combine)
    {
        dim3 grid(G3 / 32, TT);     // (96, 512)
        gemm_split_kernel<<<grid, 64>>>(p_wx_hi, p_wx_lo, p_xt_hi, p_xt_lo, p_xz, EE);
    }

    // 4) persistent recurrence: ONE kernel for all 512 steps
    recurrence_kernel<<<NCTA_REC, 192, SMEM_REC_BYTES>>>(
        p_wh_hi, p_wh_lo, p_xz, bg, bi, bo, p_c_hi, p_c_lo, out);
}